// round 16
// baseline (speedup 1.0000x reference)
#include <cuda_runtime.h>

// Problem constants
#define B_ 8
#define V_ 49
#define H_ 128
#define W_ 128
#define F_ 64

// out[b,v,h,f] = sum_w lfi[b,v,h,w] + W * h_mask[b,f,h]
//
// Champion geometry (block = one (b,h) pair, 1024 blocks, smem mask staging,
// deferred sync, L2 residency hints) upgraded to 8 warps/block:
//   grid caps residency at 7 blocks/SM, so 256-thr blocks give 56 warps/SM
//   (vs 49 with 224-thr) — +14% latency-hiding at identical traffic.
// Warp w handles v = w + 8k (k=0..5, uniform ILP-6); warp 0 also takes v=48.

__device__ __forceinline__ unsigned long long pol_evict_first() {
    unsigned long long p;
    asm("createpolicy.fractional.L2::evict_first.b64 %0, 1.0;" : "=l"(p));
    return p;
}
__device__ __forceinline__ unsigned long long pol_evict_last() {
    unsigned long long p;
    asm("createpolicy.fractional.L2::evict_last.b64 %0, 1.0;" : "=l"(p));
    return p;
}
__device__ __forceinline__ float4 ld_keep4(const float4* a, unsigned long long pol) {
    float4 v;
    asm volatile("ld.global.L2::cache_hint.v4.f32 {%0,%1,%2,%3}, [%4], %5;"
                 : "=f"(v.x), "=f"(v.y), "=f"(v.z), "=f"(v.w)
                 : "l"(a), "l"(pol));
    return v;
}
__device__ __forceinline__ void st_stream2(float2* a, float x, float y,
                                           unsigned long long pol) {
    asm volatile("st.global.L2::cache_hint.v2.f32 [%0], {%1,%2}, %3;"
                 :: "l"(a), "f"(x), "f"(y), "l"(pol) : "memory");
}

__global__ void __launch_bounds__(256, 7)
depth_cue_kernel(const float4* __restrict__ lfi4,
                 const float* __restrict__ h_mask,
                 float2* __restrict__ out2) {
    __shared__ float m_s[F_];

    const int tid  = threadIdx.x;
    const int wid  = tid >> 5;
    const int lane = tid & 31;

    const int pair = blockIdx.x;          // b*128 + h
    const int b = pair >> 7;
    const int h = pair & (H_ - 1);

    const unsigned long long pl = pol_evict_last();
    const unsigned long long pf = pol_evict_first();

    // 1) Scattered mask gather (warps 0,1 only), issued first to overlap lfi loads
    float mval = 0.0f;
    if (tid < F_) {
        mval = (float)W_ * __ldg(&h_mask[((b << 6) + tid) * H_ + h]);
    }

    // 2) Front-batched independent coalesced lfi loads.
    //    Warp w: v = w + 8k, k = 0..5 (uniform); warp 0 additionally v = 48.
    const size_t bvh0 = (size_t)(b * V_ + wid) * H_ + h;   // v = wid
    float s[6];
    #pragma unroll
    for (int k = 0; k < 6; k++) {
        const float4 v = ld_keep4(&lfi4[(bvh0 + (size_t)(8 * k) * H_) * 32 + lane], pl);
        s[k] = (v.x + v.y) + (v.z + v.w);
    }
    float s6 = 0.0f;
    const size_t row48 = (size_t)(b * V_ + 48) * H_ + h;
    if (wid == 0) {
        const float4 v = ld_keep4(&lfi4[row48 * 32 + lane], pl);
        s6 = (v.x + v.y) + (v.z + v.w);
    }

    // 3) Park mask in smem (overlapped with other warps' reduce)
    if (tid < F_) m_s[tid] = mval;

    // 4) Interleaved butterfly reductions (6-deep, +1 for warp 0)
    #pragma unroll
    for (int o = 16; o > 0; o >>= 1) {
        #pragma unroll
        for (int k = 0; k < 6; k++)
            s[k] += __shfl_xor_sync(0xffffffffu, s[k], o);
        s6 += __shfl_xor_sync(0xffffffffu, s6, o);
    }

    // 5) Barrier after all load latency is absorbed
    __syncthreads();

    // 6) Broadcast mask from smem; evict-first coalesced stores
    const float2 m = ((const float2*)m_s)[lane];
    #pragma unroll
    for (int k = 0; k < 6; k++) {
        st_stream2(&out2[(bvh0 + (size_t)(8 * k) * H_) * 32 + lane],
                   s[k] + m.x, s[k] + m.y, pf);
    }
    if (wid == 0) {
        st_stream2(&out2[row48 * 32 + lane], s6 + m.x, s6 + m.y, pf);
    }
}

extern "C" void kernel_launch(void* const* d_in, const int* in_sizes, int n_in,
                              void* d_out, int out_size) {
    // Identify inputs by element count (robust to ordering):
    //   lfi    : B*V*H*W = 6,422,528
    //   f_maps : B*H*W*F = 8,388,608 (dead input — never touched)
    //   h_mask : B*F*H   = 65,536
    const float* lfi = nullptr;
    const float* h_mask = nullptr;
    for (int i = 0; i < n_in; i++) {
        if (in_sizes[i] == B_ * V_ * H_ * W_) lfi = (const float*)d_in[i];
        else if (in_sizes[i] == B_ * F_ * H_) h_mask = (const float*)d_in[i];
    }

    // 1024 blocks (one per (b,h) pair), 256 threads (8 warps)
    depth_cue_kernel<<<B_ * H_, 256>>>((const float4*)lfi, h_mask, (float2*)d_out);
}